// round 13
// baseline (speedup 1.0000x reference)
#include <cuda_runtime.h>
#include <cuda_bf16.h>
#include <cstdint>
#include <cstddef>

// ============================================================
// AdditiveAttention via mma.sync (HMMA, valid on .target sm_103):
//   scores[b,l] = sum_h tanh(qp[b,h] + kp[b,l,h]) * w_v[h]
//   kp = keys @ W_k as 3 bf16-split GEMMs (~fp32 accuracy),
//   epilogue fused from register accumulators.
// ============================================================

constexpr int BB = 16, LKK = 8192, DD = 1024, HH = 1024;
constexpr int MTOT = BB * LKK;     // 131072 rows
constexpr int MT = 128;            // rows per CTA
constexpr int NT = 128;            // cols per n-pass
constexpr int KC = 32;             // k per chunk
constexpr int NC = DD / KC;        // 32 chunks
constexpr int NPASS = HH / NT;     // 8 passes
constexpr int THREADS = 256;       // 8 warps: 4 (m) x 2 (n)
constexpr int ROWB = 80;           // smem row pitch: 32 bf16 = 64B + 16B pad

// smem layout (bytes)
constexpr int A_OFF  = 0;
constexpr int APART  = MT * ROWB;          // 10240 (hi or lo)
constexpr int ABUF   = 2 * APART;          // 20480 per buffer
constexpr int B_OFF  = A_OFF + 2 * ABUF;   // 40960
constexpr int BPART  = NT * ROWB;
constexpr int BBUF   = 2 * BPART;
constexpr int Q_OFF  = B_OFF + 2 * BBUF;   // 81920
constexpr int WV_OFF = Q_OFF + 512;        // 82432
constexpr int RED_OFF= WV_OFF + 512;       // 82944 (2*128 floats)
constexpr int SMEM_TOTAL = RED_OFF + 1024; // 83968

// -------- device scratch (no runtime allocs allowed) --------
__device__ __align__(16) __nv_bfloat16 g_Wt_hi[(size_t)HH * DD];  // [h][d]
__device__ __align__(16) __nv_bfloat16 g_Wt_lo[(size_t)HH * DD];
__device__ float g_q[BB * HH];

// ================= asm helpers =================
__device__ __forceinline__ uint32_t smem_u32(const void* p) {
    uint32_t a;
    asm("{ .reg .u64 t; cvta.to.shared.u64 t, %1; cvt.u32.u64 %0, t; }"
        : "=r"(a) : "l"(p));
    return a;
}

#define CPASYNC16(dst, src) \
    asm volatile("cp.async.cg.shared.global [%0], [%1], 16;" \
                 :: "r"(dst), "l"(src) : "memory")
#define CPASYNC_COMMIT() asm volatile("cp.async.commit_group;" ::: "memory")
#define CPASYNC_WAIT1()  asm volatile("cp.async.wait_group 1;" ::: "memory")
#define CPASYNC_WAIT0()  asm volatile("cp.async.wait_group 0;" ::: "memory")

#define LDSM4(r, addr) \
    asm volatile("ldmatrix.sync.aligned.m8n8.x4.shared.b16 {%0,%1,%2,%3}, [%4];" \
                 : "=r"((r)[0]), "=r"((r)[1]), "=r"((r)[2]), "=r"((r)[3]) \
                 : "r"(addr))

#define MMA16816(c, a, b0, b1) \
    asm volatile("mma.sync.aligned.m16n8k16.row.col.f32.bf16.bf16.f32 " \
                 "{%0,%1,%2,%3}, {%4,%5,%6,%7}, {%8,%9}, {%0,%1,%2,%3};" \
                 : "+f"((c)[0]), "+f"((c)[1]), "+f"((c)[2]), "+f"((c)[3]) \
                 : "r"((a)[0]), "r"((a)[1]), "r"((a)[2]), "r"((a)[3]), \
                   "r"(b0), "r"(b1))

__device__ __forceinline__ uint32_t pk2(__nv_bfloat16 a, __nv_bfloat16 b) {
    __nv_bfloat162 t(a, b);
    uint32_t r;
    memcpy(&r, &t, 4);
    return r;
}

// split a float4 into hi/lo bf16 packs (exact residual split)
__device__ __forceinline__ void split4(float4 v, uint2& hp, uint2& lp) {
    __nv_bfloat16 h0 = __float2bfloat16(v.x);
    __nv_bfloat16 h1 = __float2bfloat16(v.y);
    __nv_bfloat16 h2 = __float2bfloat16(v.z);
    __nv_bfloat16 h3 = __float2bfloat16(v.w);
    __nv_bfloat16 l0 = __float2bfloat16(v.x - __bfloat162float(h0));
    __nv_bfloat16 l1 = __float2bfloat16(v.y - __bfloat162float(h1));
    __nv_bfloat16 l2 = __float2bfloat16(v.z - __bfloat162float(h2));
    __nv_bfloat16 l3 = __float2bfloat16(v.w - __bfloat162float(h3));
    hp.x = pk2(h0, h1); hp.y = pk2(h2, h3);
    lp.x = pk2(l0, l1); lp.y = pk2(l2, l3);
}

// ================= prep kernels =================

// g_q[b][h] = sum_d queries[b,d] * W_q[d,h]  (fp32, tiny)
__global__ void qproj_kernel(const float* __restrict__ queries,
                             const float* __restrict__ Wq) {
    __shared__ float qrow[DD];
    const int b = blockIdx.x;
    for (int i = threadIdx.x; i < DD; i += THREADS)
        qrow[i] = queries[(size_t)b * DD + i];
    __syncthreads();
    float a0 = 0.f, a1 = 0.f, a2 = 0.f, a3 = 0.f;
    const int h = threadIdx.x;
    for (int d = 0; d < DD; ++d) {
        const float qv = qrow[d];
        const float* wr = Wq + (size_t)d * HH + h;
        a0 += qv * wr[0];
        a1 += qv * wr[256];
        a2 += qv * wr[512];
        a3 += qv * wr[768];
    }
    g_q[b * HH + h]       = a0;
    g_q[b * HH + h + 256] = a1;
    g_q[b * HH + h + 512] = a2;
    g_q[b * HH + h + 768] = a3;
}

// W_k [d][h] fp32 -> transposed bf16 hi/lo  g_Wt[h][d]
__global__ void wsplit_kernel(const float* __restrict__ Wk) {
    __shared__ float tile[32][33];
    const int h0 = blockIdx.x * 32;
    const int d0 = blockIdx.y * 32;
    const int tx = threadIdx.x;
    for (int j = threadIdx.y; j < 32; j += 8)
        tile[j][tx] = Wk[(size_t)(d0 + j) * HH + (h0 + tx)];
    __syncthreads();
    const int dx = d0 + tx;
    for (int j = threadIdx.y; j < 32; j += 8) {
        float v = tile[tx][j];  // = Wk[d0+tx][h0+j]
        __nv_bfloat16 hi = __float2bfloat16(v);
        __nv_bfloat16 lo = __float2bfloat16(v - __bfloat162float(hi));
        g_Wt_hi[(size_t)(h0 + j) * DD + dx] = hi;
        g_Wt_lo[(size_t)(h0 + j) * DD + dx] = lo;
    }
}

// ================= main fused kernel =================
__global__ void __launch_bounds__(THREADS, 1)
additive_attn_main(const float* __restrict__ keys,
                   const float* __restrict__ wv,
                   float* __restrict__ out) {
    extern __shared__ char smem[];
    const uint32_t sb = smem_u32(smem);
    const int tid  = threadIdx.x;
    const int lane = tid & 31;
    const int wid  = tid >> 5;
    const int wm   = wid >> 1;   // 0..3 -> 32 rows each
    const int wn   = wid & 1;    // 0..1 -> 64 cols each
    const int m0   = blockIdx.x * MT;
    const int b    = m0 >> 13;   // 8192 rows per batch

    float* q_s  = reinterpret_cast<float*>(smem + Q_OFF);
    float* wv_s = reinterpret_cast<float*>(smem + WV_OFF);
    float* red  = reinterpret_cast<float*>(smem + RED_OFF);

    // per-lane ldmatrix offsets
    const uint32_t a_lane = (uint32_t)((lane % 16) * ROWB + (lane / 16) * 16);
    const uint32_t b_lane = (uint32_t)(((lane & 7) + ((lane >> 4) << 3)) * ROWB
                                       + ((lane & 8) ? 16 : 0));

    float sc00 = 0.f, sc01 = 0.f, sc10 = 0.f, sc11 = 0.f;

    for (int np = 0; np < NPASS; ++np) {
        const int n0 = np * NT;
        __syncthreads();  // protect q_s/wv_s vs previous pass epilogue
        if (tid < NT) {
            q_s[tid]  = g_q[b * HH + n0 + tid];
            wv_s[tid] = wv[n0 + tid];
        }

        float acc[2][8][4];
        #pragma unroll
        for (int mi = 0; mi < 2; ++mi)
            #pragma unroll
            for (int ni = 0; ni < 8; ++ni)
                #pragma unroll
                for (int c = 0; c < 4; ++c) acc[mi][ni][c] = 0.f;

        // ---------- prologue: chunk 0 into buffer 0 ----------
        {
            #pragma unroll
            for (int t = 0; t < 4; ++t) {   // B via cp.async
                const int j = t * 256 + tid;
                const int part = j >> 9, idx = j & 511;
                const int row = idx >> 2, seg = idx & 3;
                const __nv_bfloat16* src =
                    (part ? g_Wt_lo : g_Wt_hi) + (size_t)(n0 + row) * DD + seg * 8;
                const uint32_t dst = sb + B_OFF + part * BPART + row * ROWB + seg * 16;
                CPASYNC16(dst, src);
            }
            CPASYNC_COMMIT();
            #pragma unroll
            for (int t = 0; t < 4; ++t) {   // A: LDG fp32 -> split -> STS
                const int j = t * 256 + tid;
                const int row = j >> 3, seg = j & 7;
                float4 v = *reinterpret_cast<const float4*>(
                    keys + (size_t)(m0 + row) * DD + seg * 4);
                uint2 hp, lp; split4(v, hp, lp);
                *reinterpret_cast<uint2*>(smem + A_OFF + row * ROWB + seg * 8) = hp;
                *reinterpret_cast<uint2*>(smem + A_OFF + APART + row * ROWB + seg * 8) = lp;
            }
        }

        float4 stage[4];

        #pragma unroll 1
        for (int kc = 0; kc < NC; ++kc) {
            const int buf = kc & 1, nbuf = buf ^ 1;
            const bool more = (kc + 1 < NC);
            if (more) {
                const int kn = kc + 1;
                #pragma unroll
                for (int t = 0; t < 4; ++t) {  // next B tiles
                    const int j = t * 256 + tid;
                    const int part = j >> 9, idx = j & 511;
                    const int row = idx >> 2, seg = idx & 3;
                    const __nv_bfloat16* src = (part ? g_Wt_lo : g_Wt_hi)
                        + (size_t)(n0 + row) * DD + kn * KC + seg * 8;
                    const uint32_t dst =
                        sb + B_OFF + nbuf * BBUF + part * BPART + row * ROWB + seg * 16;
                    CPASYNC16(dst, src);
                }
                CPASYNC_COMMIT();
                #pragma unroll
                for (int t = 0; t < 4; ++t) {  // next A keys into regs
                    const int j = t * 256 + tid;
                    const int row = j >> 3, seg = j & 7;
                    stage[t] = *reinterpret_cast<const float4*>(
                        keys + (size_t)(m0 + row) * DD + kn * KC + seg * 4);
                }
                CPASYNC_WAIT1();
            } else {
                CPASYNC_WAIT0();
            }
            __syncthreads();

            // ---------- MMA over current chunk ----------
            const uint32_t Abase = sb + A_OFF + buf * ABUF;
            const uint32_t Bbase = sb + B_OFF + buf * BBUF;
            #pragma unroll
            for (int ks = 0; ks < 2; ++ks) {     // two k16 steps per chunk
                const uint32_t koff = ks * 32;
                uint32_t ah[2][4], al[2][4];
                #pragma unroll
                for (int mi = 0; mi < 2; ++mi) {
                    const uint32_t ra = Abase + (wm * 32 + mi * 16) * ROWB + a_lane + koff;
                    LDSM4(ah[mi], ra);
                    LDSM4(al[mi], ra + APART);
                }
                #pragma unroll
                for (int nq = 0; nq < 4; ++nq) { // 2 n-frags per ldmatrix.x4
                    const uint32_t rb = Bbase + (wn * 64 + nq * 16) * ROWB + b_lane + koff;
                    uint32_t bh[4], bl[4];
                    LDSM4(bh, rb);
                    LDSM4(bl, rb + BPART);
                    // product-major order: same accumulator touched every 4 mmas
                    #pragma unroll
                    for (int h2 = 0; h2 < 2; ++h2)
                        #pragma unroll
                        for (int mi = 0; mi < 2; ++mi)
                            MMA16816(acc[mi][nq * 2 + h2], ah[mi], bh[h2 * 2], bh[h2 * 2 + 1]);
                    #pragma unroll
                    for (int h2 = 0; h2 < 2; ++h2)
                        #pragma unroll
                        for (int mi = 0; mi < 2; ++mi)
                            MMA16816(acc[mi][nq * 2 + h2], ah[mi], bl[h2 * 2], bl[h2 * 2 + 1]);
                    #pragma unroll
                    for (int h2 = 0; h2 < 2; ++h2)
                        #pragma unroll
                        for (int mi = 0; mi < 2; ++mi)
                            MMA16816(acc[mi][nq * 2 + h2], al[mi], bh[h2 * 2], bh[h2 * 2 + 1]);
                }
            }

            if (more) {
                #pragma unroll
                for (int t = 0; t < 4; ++t) {   // store staged next-A
                    const int j = t * 256 + tid;
                    const int row = j >> 3, seg = j & 7;
                    uint2 hp, lp; split4(stage[t], hp, lp);
                    *reinterpret_cast<uint2*>(
                        smem + A_OFF + nbuf * ABUF + row * ROWB + seg * 8) = hp;
                    *reinterpret_cast<uint2*>(
                        smem + A_OFF + nbuf * ABUF + APART + row * ROWB + seg * 8) = lp;
                }
            }
        }

        // ---------- fused epilogue: tanh + dot with w_v ----------
        #pragma unroll
        for (int mi = 0; mi < 2; ++mi) {
            #pragma unroll
            for (int ni = 0; ni < 8; ++ni) {
                const int col0 = wn * 64 + ni * 8 + (lane & 3) * 2;
                const float q0 = q_s[col0],     q1 = q_s[col0 + 1];
                const float w0 = wv_s[col0],    w1 = wv_s[col0 + 1];
                const float* c = acc[mi][ni];
                const float p0 = tanhf(c[0] + q0) * w0 + tanhf(c[1] + q1) * w1;
                const float p1 = tanhf(c[2] + q0) * w0 + tanhf(c[3] + q1) * w1;
                if (mi == 0) { sc00 += p0; sc01 += p1; }
                else         { sc10 += p0; sc11 += p1; }
            }
        }
    }

    // ---------- final reduction ----------
    sc00 += __shfl_xor_sync(~0u, sc00, 1); sc00 += __shfl_xor_sync(~0u, sc00, 2);
    sc01 += __shfl_xor_sync(~0u, sc01, 1); sc01 += __shfl_xor_sync(~0u, sc01, 2);
    sc10 += __shfl_xor_sync(~0u, sc10, 1); sc10 += __shfl_xor_sync(~0u, sc10, 2);
    sc11 += __shfl_xor_sync(~0u, sc11, 1); sc11 += __shfl_xor_sync(~0u, sc11, 2);
    if ((lane & 3) == 0) {
        const int g = lane >> 2;
        red[wn * 128 + wm * 32 + g]      = sc00;
        red[wn * 128 + wm * 32 + 8 + g]  = sc01;
        red[wn * 128 + wm * 32 + 16 + g] = sc10;
        red[wn * 128 + wm * 32 + 24 + g] = sc11;
    }
    __syncthreads();
    if (tid < MT) out[m0 + tid] = red[tid] + red[128 + tid];
}

// ================= launch =================
extern "C" void kernel_launch(void* const* d_in, const int* in_sizes, int n_in,
                              void* d_out, int out_size) {
    const float* queries = (const float*)d_in[0];  // [16,1,1024]
    const float* keys    = (const float*)d_in[1];  // [16,8192,1024]
    const float* Wq      = (const float*)d_in[2];  // [1024,1024]
    const float* Wk      = (const float*)d_in[3];  // [1024,1024]
    const float* wv      = (const float*)d_in[4];  // [1024,1]
    float* out = (float*)d_out;                    // [16,8192]

    cudaFuncSetAttribute(additive_attn_main,
                         cudaFuncAttributeMaxDynamicSharedMemorySize, SMEM_TOTAL);

    qproj_kernel<<<BB, THREADS>>>(queries, Wq);
    wsplit_kernel<<<dim3(HH / 32, DD / 32), dim3(32, 8)>>>(Wk);
    additive_attn_main<<<MTOT / MT, THREADS, SMEM_TOTAL>>>(keys, wv, out);
}

// round 15
// speedup vs baseline: 2.4471x; 2.4471x over previous
#include <cuda_runtime.h>
#include <cuda_bf16.h>
#include <cuda_fp16.h>
#include <cstdint>
#include <cstddef>

// ============================================================
// AdditiveAttention via single fp16 mma.sync GEMM (legal on .target sm_103):
//   scores[b,l] = sum_h tanh(qp[b,h] + kp[b,l,h]) * w_v[h]
// Race-free double buffering: barrier AFTER each MMA section orders
// next iteration's cp.async writes against this iteration's ldmatrix reads.
// ============================================================

constexpr int BB = 16, LKK = 8192, DD = 1024, HH = 1024;
constexpr int MTOT = BB * LKK;     // 131072 rows
constexpr int MT = 128;            // rows per CTA
constexpr int NT = 128;            // cols per n-pass
constexpr int KC = 64;             // k per chunk
constexpr int NC = DD / KC;        // 16 chunks
constexpr int NPASS = HH / NT;     // 8 passes
constexpr int THREADS = 256;       // 8 warps: 4 (m) x 2 (n)
constexpr int ROWB = 144;          // smem pitch: 64 fp16 = 128B + 16B pad

// smem layout (bytes)
constexpr int A_OFF  = 0;
constexpr int ATILE  = MT * ROWB;            // 18432
constexpr int B_OFF  = A_OFF + 2 * ATILE;    // 36864
constexpr int BTILE  = NT * ROWB;            // 18432
constexpr int Q_OFF  = B_OFF + 2 * BTILE;    // 73728
constexpr int WV_OFF = Q_OFF + 512;          // 74240
constexpr int RED_OFF= WV_OFF + 512;         // 74752
constexpr int SMEM_TOTAL = RED_OFF + 1024;   // 75776
static_assert(2 * SMEM_TOTAL <= 227 * 1024, "2 CTA/SM smem");

// -------- device scratch (no runtime allocs allowed) --------
__device__ __align__(16) __half g_keysh[(size_t)MTOT * DD];   // 256 MB fp16 keys
__device__ __align__(16) __half g_Wth[(size_t)HH * DD];       // W_k^T fp16 [h][d]
__device__ float g_q[BB * HH];

// ================= asm helpers =================
__device__ __forceinline__ uint32_t smem_u32(const void* p) {
    uint32_t a;
    asm("{ .reg .u64 t; cvta.to.shared.u64 t, %1; cvt.u32.u64 %0, t; }"
        : "=r"(a) : "l"(p));
    return a;
}

#define CPASYNC16(dst, src) \
    asm volatile("cp.async.cg.shared.global [%0], [%1], 16;" \
                 :: "r"(dst), "l"(src) : "memory")
#define CPASYNC_COMMIT() asm volatile("cp.async.commit_group;" ::: "memory")
#define CPASYNC_WAIT1()  asm volatile("cp.async.wait_group 1;" ::: "memory")
#define CPASYNC_WAIT0()  asm volatile("cp.async.wait_group 0;" ::: "memory")

#define LDSM4(r, addr) \
    asm volatile("ldmatrix.sync.aligned.m8n8.x4.shared.b16 {%0,%1,%2,%3}, [%4];" \
                 : "=r"((r)[0]), "=r"((r)[1]), "=r"((r)[2]), "=r"((r)[3]) \
                 : "r"(addr))

#define MMA16816(c, a, b0, b1) \
    asm volatile("mma.sync.aligned.m16n8k16.row.col.f32.f16.f16.f32 " \
                 "{%0,%1,%2,%3}, {%4,%5,%6,%7}, {%8,%9}, {%0,%1,%2,%3};" \
                 : "+f"((c)[0]), "+f"((c)[1]), "+f"((c)[2]), "+f"((c)[3]) \
                 : "r"((a)[0]), "r"((a)[1]), "r"((a)[2]), "r"((a)[3]), \
                   "r"(b0), "r"(b1))

// ================= prep kernels =================

// keys fp32 -> fp16 (round-nearest)
__global__ void convert_keys_kernel(const float* __restrict__ keys) {
    const size_t total4 = (size_t)MTOT * DD / 4;
    const size_t stride = (size_t)gridDim.x * blockDim.x;
    __half2* dst = reinterpret_cast<__half2*>(g_keysh);
    for (size_t i = (size_t)blockIdx.x * blockDim.x + threadIdx.x; i < total4; i += stride) {
        float4 v = reinterpret_cast<const float4*>(keys)[i];
        dst[2 * i]     = __floats2half2_rn(v.x, v.y);
        dst[2 * i + 1] = __floats2half2_rn(v.z, v.w);
    }
}

// W_k [d][h] fp32 -> transposed fp16  g_Wth[h][d]
__global__ void wsplit_kernel(const float* __restrict__ Wk) {
    __shared__ float tile[32][33];
    const int h0 = blockIdx.x * 32;
    const int d0 = blockIdx.y * 32;
    const int tx = threadIdx.x;
    for (int j = threadIdx.y; j < 32; j += 8)
        tile[j][tx] = Wk[(size_t)(d0 + j) * HH + (h0 + tx)];
    __syncthreads();
    const int dx = d0 + tx;
    for (int j = threadIdx.y; j < 32; j += 8)
        g_Wth[(size_t)(h0 + j) * DD + dx] = __float2half_rn(tile[tx][j]);
}

// g_q[b][h] = sum_d queries[b,d] * W_q[d,h]; grid (H/256, BB)
__global__ void qproj_kernel(const float* __restrict__ queries,
                             const float* __restrict__ Wq) {
    __shared__ float qrow[DD];
    const int b = blockIdx.y;
    const int h = blockIdx.x * 256 + threadIdx.x;
    for (int i = threadIdx.x; i < DD; i += 256)
        qrow[i] = queries[(size_t)b * DD + i];
    __syncthreads();
    float acc = 0.f;
    #pragma unroll 8
    for (int d = 0; d < DD; ++d)
        acc += qrow[d] * Wq[(size_t)d * HH + h];
    g_q[b * HH + h] = acc;
}

// ================= main fused kernel =================
__global__ void __launch_bounds__(THREADS, 2)
additive_attn_main(const float* __restrict__ wv, float* __restrict__ out) {
    extern __shared__ char smem[];
    const uint32_t sb = smem_u32(smem);
    const int tid  = threadIdx.x;
    const int lane = tid & 31;
    const int wid  = tid >> 5;
    const int wm   = wid >> 1;   // 0..3 -> 32 rows each
    const int wn   = wid & 1;    // 0..1 -> 64 cols each
    const int m0   = blockIdx.x * MT;
    const int b    = m0 >> 13;   // 8192 rows per batch

    float* q_s  = reinterpret_cast<float*>(smem + Q_OFF);
    float* wv_s = reinterpret_cast<float*>(smem + WV_OFF);
    float* red  = reinterpret_cast<float*>(smem + RED_OFF);

    // per-lane ldmatrix offsets (validated in R13)
    const uint32_t a_lane = (uint32_t)((lane % 16) * ROWB + (lane / 16) * 16);
    const uint32_t b_lane = (uint32_t)(((lane & 7) + ((lane >> 4) << 3)) * ROWB
                                       + ((lane & 8) ? 16 : 0));

    float sc00 = 0.f, sc01 = 0.f, sc10 = 0.f, sc11 = 0.f;

    for (int np = 0; np < NPASS; ++np) {
        const int n0 = np * NT;
        __syncthreads();  // prev-pass epilogue (q_s/wv_s reads) done
        if (tid < NT) {
            q_s[tid]  = g_q[b * HH + n0 + tid];
            wv_s[tid] = wv[n0 + tid];
        }

        float acc[2][8][4];
        #pragma unroll
        for (int mi = 0; mi < 2; ++mi)
            #pragma unroll
            for (int ni = 0; ni < 8; ++ni)
                #pragma unroll
                for (int c = 0; c < 4; ++c) acc[mi][ni][c] = 0.f;

        // ---------- prologue: chunk 0 into buffer 0 ----------
        // (safe: previous pass's last reads of buf0 were fenced by the
        //  trailing barrier of chunk NC-2 and the pass-top barrier)
        #pragma unroll
        for (int t = 0; t < 4; ++t) {
            const int j = t * 256 + tid;
            const int row = j >> 3, seg = j & 7;
            CPASYNC16(sb + A_OFF + row * ROWB + seg * 16,
                      g_keysh + (size_t)(m0 + row) * DD + seg * 8);
            CPASYNC16(sb + B_OFF + row * ROWB + seg * 16,
                      g_Wth + (size_t)(n0 + row) * DD + seg * 8);
        }
        CPASYNC_COMMIT();

        #pragma unroll 1
        for (int kc = 0; kc < NC; ++kc) {
            const int buf = kc & 1, nbuf = buf ^ 1;
            if (kc + 1 < NC) {
                // writes into nbuf: all reads of nbuf (iter kc-1) were
                // fenced by the post-MMA barrier of iter kc-1.
                const int k0 = (kc + 1) * KC;
                #pragma unroll
                for (int t = 0; t < 4; ++t) {
                    const int j = t * 256 + tid;
                    const int row = j >> 3, seg = j & 7;
                    CPASYNC16(sb + A_OFF + nbuf * ATILE + row * ROWB + seg * 16,
                              g_keysh + (size_t)(m0 + row) * DD + k0 + seg * 8);
                    CPASYNC16(sb + B_OFF + nbuf * BTILE + row * ROWB + seg * 16,
                              g_Wth + (size_t)(n0 + row) * DD + k0 + seg * 8);
                }
                CPASYNC_COMMIT();
                CPASYNC_WAIT1();
            } else {
                CPASYNC_WAIT0();
            }
            __syncthreads();   // barrier #1: buf data visible to all warps

            const uint32_t Abase = sb + A_OFF + buf * ATILE;
            const uint32_t Bbase = sb + B_OFF + buf * BTILE;
            #pragma unroll
            for (int ks = 0; ks < KC / 16; ++ks) {   // 4 k16 steps
                const uint32_t koff = ks * 32;       // 16 fp16 = 32 B
                uint32_t ah[2][4];
                #pragma unroll
                for (int mi = 0; mi < 2; ++mi)
                    LDSM4(ah[mi], Abase + (wm * 32 + mi * 16) * ROWB + a_lane + koff);
                #pragma unroll
                for (int nq = 0; nq < 4; ++nq) {     // 16 n per ldsm.x4
                    uint32_t bh[4];
                    LDSM4(bh, Bbase + (wn * 64 + nq * 16) * ROWB + b_lane + koff);
                    #pragma unroll
                    for (int h2 = 0; h2 < 2; ++h2)
                        #pragma unroll
                        for (int mi = 0; mi < 2; ++mi)
                            MMA16816(acc[mi][nq * 2 + h2], ah[mi],
                                     bh[h2 * 2], bh[h2 * 2 + 1]);
                }
            }
            __syncthreads();   // barrier #2 (RACE FIX): all warps finished
                               // reading buf before next iter's cp.async
                               // overwrites it
        }

        // ---------- fused epilogue: tanh + dot with w_v ----------
        #pragma unroll
        for (int mi = 0; mi < 2; ++mi) {
            #pragma unroll
            for (int ni = 0; ni < 8; ++ni) {
                const int col0 = wn * 64 + ni * 8 + (lane & 3) * 2;
                const float q0 = q_s[col0],  q1 = q_s[col0 + 1];
                const float w0 = wv_s[col0], w1 = wv_s[col0 + 1];
                const float* c = acc[mi][ni];
                const float p0 = tanhf(c[0] + q0) * w0 + tanhf(c[1] + q1) * w1;
                const float p1 = tanhf(c[2] + q0) * w0 + tanhf(c[3] + q1) * w1;
                if (mi == 0) { sc00 += p0; sc01 += p1; }
                else         { sc10 += p0; sc11 += p1; }
            }
        }
    }

    // ---------- final reduction ----------
    sc00 += __shfl_xor_sync(~0u, sc00, 1); sc00 += __shfl_xor_sync(~0u, sc00, 2);
    sc01 += __shfl_xor_sync(~0u, sc01, 1); sc01 += __shfl_xor_sync(~0u, sc01, 2);
    sc10 += __shfl_xor_sync(~0u, sc10, 1); sc10 += __shfl_xor_sync(~0u, sc10, 2);
    sc11 += __shfl_xor_sync(~0u, sc11, 1); sc11 += __shfl_xor_sync(~0u, sc11, 2);
    if ((lane & 3) == 0) {
        const int g = lane >> 2;
        red[wn * 128 + wm * 32 + g]      = sc00;
        red[wn * 128 + wm * 32 + 8 + g]  = sc01;
        red[wn * 128 + wm * 32 + 16 + g] = sc10;
        red[wn * 128 + wm * 32 + 24 + g] = sc11;
    }
    __syncthreads();
    if (tid < MT) out[m0 + tid] = red[tid] + red[128 + tid];
}

// ================= launch =================
extern "C" void kernel_launch(void* const* d_in, const int* in_sizes, int n_in,
                              void* d_out, int out_size) {
    const float* queries = (const float*)d_in[0];  // [16,1,1024]
    const float* keys    = (const float*)d_in[1];  // [16,8192,1024]
    const float* Wq      = (const float*)d_in[2];  // [1024,1024]
    const float* Wk      = (const float*)d_in[3];  // [1024,1024]
    const float* wv      = (const float*)d_in[4];  // [1024,1]
    float* out = (float*)d_out;                    // [16,8192]

    cudaFuncSetAttribute(additive_attn_main,
                         cudaFuncAttributeMaxDynamicSharedMemorySize, SMEM_TOTAL);

    convert_keys_kernel<<<2048, 256>>>(keys);
    wsplit_kernel<<<dim3(HH / 32, DD / 32), dim3(32, 8)>>>(Wk);
    qproj_kernel<<<dim3(HH / 256, BB), 256>>>(queries, Wq);
    additive_attn_main<<<MTOT / MT, THREADS, SMEM_TOTAL>>>(wv, out);
}

// round 16
// speedup vs baseline: 2.6092x; 1.0662x over previous
#include <cuda_runtime.h>
#include <cuda_bf16.h>
#include <cuda_fp16.h>
#include <cstdint>
#include <cstddef>

// ============================================================
// AdditiveAttention via single fp16 mma.sync GEMM:
//   scores[b,l] = sum_h tanh(qp[b,h] + kp[b,l,h]) * w_v[h]
// 3-stage continuous cp.async pipeline, ONE barrier per chunk,
// no pass-boundary drain. Provably race-free: buffer written at
// iter c was last read at iter c-1, ordered by the barrier at
// top of iter c (issue happens after the barrier).
// ============================================================

constexpr int BB = 16, LKK = 8192, DD = 1024, HH = 1024;
constexpr int MTOT = BB * LKK;     // 131072 rows
constexpr int MT = 128;            // rows per CTA
constexpr int NT = 128;            // cols per n-pass
constexpr int KC = 64;             // k per chunk
constexpr int NC = DD / KC;        // 16 chunks per pass
constexpr int NPASS = HH / NT;     // 8 passes
constexpr int TOTC = NPASS * NC;   // 128 chunks, flat
constexpr int THREADS = 256;       // 8 warps: 4 (m) x 2 (n)
constexpr int ROWB = 144;          // smem pitch: 64 fp16 = 128B + 16B pad

// smem layout (bytes)
constexpr int ATILE  = MT * ROWB;            // 18432
constexpr int BTILE  = NT * ROWB;            // 18432
constexpr int STAGE  = ATILE + BTILE;        // 36864
constexpr int Q_OFF  = 3 * STAGE;            // 110592 (2 x 128 floats)
constexpr int WV_OFF = Q_OFF + 1024;         // 111616 (2 x 128 floats)
constexpr int RED_OFF= WV_OFF + 1024;        // 112640 (256 floats)
constexpr int SMEM_TOTAL = RED_OFF + 1024;   // 113664
static_assert(2 * SMEM_TOTAL <= 232448 - 2048, "2 CTA/SM smem");

// -------- device scratch (no runtime allocs allowed) --------
__device__ __align__(16) __half g_keysh[(size_t)MTOT * DD];   // 256 MB fp16 keys
__device__ __align__(16) __half g_Wth[(size_t)HH * DD];       // W_k^T fp16 [h][d]
__device__ float g_q[BB * HH];

// ================= asm helpers =================
__device__ __forceinline__ uint32_t smem_u32(const void* p) {
    uint32_t a;
    asm("{ .reg .u64 t; cvta.to.shared.u64 t, %1; cvt.u32.u64 %0, t; }"
        : "=r"(a) : "l"(p));
    return a;
}

#define CPASYNC16(dst, src) \
    asm volatile("cp.async.cg.shared.global [%0], [%1], 16;" \
                 :: "r"(dst), "l"(src) : "memory")
#define CPASYNC_COMMIT() asm volatile("cp.async.commit_group;" ::: "memory")
#define CPASYNC_WAIT1()  asm volatile("cp.async.wait_group 1;" ::: "memory")
#define CPASYNC_WAIT0()  asm volatile("cp.async.wait_group 0;" ::: "memory")

#define LDSM4(r, addr) \
    asm volatile("ldmatrix.sync.aligned.m8n8.x4.shared.b16 {%0,%1,%2,%3}, [%4];" \
                 : "=r"((r)[0]), "=r"((r)[1]), "=r"((r)[2]), "=r"((r)[3]) \
                 : "r"(addr))

#define MMA16816(c, a, b0, b1) \
    asm volatile("mma.sync.aligned.m16n8k16.row.col.f32.f16.f16.f32 " \
                 "{%0,%1,%2,%3}, {%4,%5,%6,%7}, {%8,%9}, {%0,%1,%2,%3};" \
                 : "+f"((c)[0]), "+f"((c)[1]), "+f"((c)[2]), "+f"((c)[3]) \
                 : "r"((a)[0]), "r"((a)[1]), "r"((a)[2]), "r"((a)[3]), \
                   "r"(b0), "r"(b1))

// ================= prep kernels =================

// keys fp32 -> fp16 (round-nearest)
__global__ void convert_keys_kernel(const float* __restrict__ keys) {
    const size_t total4 = (size_t)MTOT * DD / 4;
    const size_t stride = (size_t)gridDim.x * blockDim.x;
    __half2* dst = reinterpret_cast<__half2*>(g_keysh);
    for (size_t i = (size_t)blockIdx.x * blockDim.x + threadIdx.x; i < total4; i += stride) {
        float4 v = reinterpret_cast<const float4*>(keys)[i];
        dst[2 * i]     = __floats2half2_rn(v.x, v.y);
        dst[2 * i + 1] = __floats2half2_rn(v.z, v.w);
    }
}

// W_k [d][h] fp32 -> transposed fp16  g_Wth[h][d]
__global__ void wsplit_kernel(const float* __restrict__ Wk) {
    __shared__ float tile[32][33];
    const int h0 = blockIdx.x * 32;
    const int d0 = blockIdx.y * 32;
    const int tx = threadIdx.x;
    for (int j = threadIdx.y; j < 32; j += 8)
        tile[j][tx] = Wk[(size_t)(d0 + j) * HH + (h0 + tx)];
    __syncthreads();
    const int dx = d0 + tx;
    for (int j = threadIdx.y; j < 32; j += 8)
        g_Wth[(size_t)(h0 + j) * DD + dx] = __float2half_rn(tile[tx][j]);
}

// g_q[b][h] = sum_d queries[b,d] * W_q[d,h]; grid (H/256, BB)
__global__ void qproj_kernel(const float* __restrict__ queries,
                             const float* __restrict__ Wq) {
    __shared__ float qrow[DD];
    const int b = blockIdx.y;
    const int h = blockIdx.x * 256 + threadIdx.x;
    for (int i = threadIdx.x; i < DD; i += 256)
        qrow[i] = queries[(size_t)b * DD + i];
    __syncthreads();
    float acc = 0.f;
    #pragma unroll 8
    for (int d = 0; d < DD; ++d)
        acc += qrow[d] * Wq[(size_t)d * HH + h];
    g_q[b * HH + h] = acc;
}

// ================= main fused kernel =================
__global__ void __launch_bounds__(THREADS, 2)
additive_attn_main(const float* __restrict__ wv, float* __restrict__ out) {
    extern __shared__ char smem[];
    const uint32_t sb = smem_u32(smem);
    const int tid  = threadIdx.x;
    const int lane = tid & 31;
    const int wid  = tid >> 5;
    const int wm   = wid >> 1;   // 0..3 -> 32 rows each
    const int wn   = wid & 1;    // 0..1 -> 64 cols each
    const int m0   = blockIdx.x * MT;
    const int b    = m0 >> 13;   // 8192 rows per batch

    float* q_s  = reinterpret_cast<float*>(smem + Q_OFF);   // [2][128]
    float* wv_s = reinterpret_cast<float*>(smem + WV_OFF);  // [2][128]
    float* red  = reinterpret_cast<float*>(smem + RED_OFF);

    // per-lane ldmatrix offsets (verified R13/R15)
    const uint32_t a_lane = (uint32_t)((lane % 16) * ROWB + (lane / 16) * 16);
    const uint32_t b_lane = (uint32_t)(((lane & 7) + ((lane >> 4) << 3)) * ROWB
                                       + ((lane & 8) ? 16 : 0));

    // per-thread copy coordinates (constant across chunks)
    const int crow = tid >> 3;   // 0..31
    const int cseg = tid & 7;    // 0..7
    const __half* asrc0 = g_keysh + (size_t)(m0 + crow) * DD + cseg * 8;
    const __half* bsrc0 = g_Wth + (size_t)crow * DD + cseg * 8;
    const uint32_t dst0 = (uint32_t)(crow * ROWB + cseg * 16);

    // issue one chunk's cp.asyncs + commit
    auto issue_chunk = [&](int c) {
        const int k0 = (c & (NC - 1)) * KC;
        const size_t boff = (size_t)((c >> 4) * NT) * DD + k0;
        const uint32_t stg = sb + (c % 3) * STAGE;
        #pragma unroll
        for (int t = 0; t < 4; ++t) {
            CPASYNC16(stg + dst0 + t * 32 * ROWB,
                      asrc0 + (size_t)t * 32 * DD + k0);
            CPASYNC16(stg + ATILE + dst0 + t * 32 * ROWB,
                      bsrc0 + (size_t)t * 32 * DD + boff);
        }
        CPASYNC_COMMIT();
    };

    float sc00 = 0.f, sc01 = 0.f, sc10 = 0.f, sc11 = 0.f;
    float acc[2][8][4];
    #pragma unroll
    for (int mi = 0; mi < 2; ++mi)
        #pragma unroll
        for (int ni = 0; ni < 8; ++ni)
            #pragma unroll
            for (int cc = 0; cc < 4; ++cc) acc[mi][ni][cc] = 0.f;

    // prologue: chunks 0 and 1 in flight; stage pass-0 q/wv
    issue_chunk(0);
    issue_chunk(1);
    if (tid < NT) {
        q_s[tid]  = g_q[b * HH + tid];
        wv_s[tid] = wv[tid];
    }

    #pragma unroll 1
    for (int c = 0; c < TOTC; ++c) {
        if (c + 1 < TOTC) { CPASYNC_WAIT1(); } else { CPASYNC_WAIT0(); }
        __syncthreads();   // chunk c visible; orders iter c-1 reads of
                           // buffer (c+2)%3 before the writes below

        if (c + 2 < TOTC) issue_chunk(c + 2);

        // stage q/wv for the NEXT pass at each pass start (reader is the
        // epilogue of that pass, 15+ barriers later; previous reader of the
        // same parity buffer finished 1 barrier ago)
        if ((c & (NC - 1)) == 0 && (c >> 4) + 1 < NPASS && tid < NT) {
            const int npn = (c >> 4) + 1;
            q_s[(npn & 1) * 128 + tid]  = g_q[b * HH + npn * NT + tid];
            wv_s[(npn & 1) * 128 + tid] = wv[npn * NT + tid];
        }

        // ---------- MMA over chunk c ----------
        const uint32_t Abase = sb + (c % 3) * STAGE;
        const uint32_t Bbase = Abase + ATILE;
        #pragma unroll
        for (int ks = 0; ks < KC / 16; ++ks) {   // 4 k16 steps
            const uint32_t koff = ks * 32;       // 16 fp16 = 32 B
            uint32_t ah[2][4];
            #pragma unroll
            for (int mi = 0; mi < 2; ++mi)
                LDSM4(ah[mi], Abase + (wm * 32 + mi * 16) * ROWB + a_lane + koff);
            #pragma unroll
            for (int nq = 0; nq < 4; ++nq) {     // 16 n per ldsm.x4
                uint32_t bh[4];
                LDSM4(bh, Bbase + (wn * 64 + nq * 16) * ROWB + b_lane + koff);
                #pragma unroll
                for (int h2 = 0; h2 < 2; ++h2)
                    #pragma unroll
                    for (int mi = 0; mi < 2; ++mi)
                        MMA16816(acc[mi][nq * 2 + h2], ah[mi],
                                 bh[h2 * 2], bh[h2 * 2 + 1]);
            }
        }

        // ---------- pass epilogue: tanh + dot with w_v ----------
        if ((c & (NC - 1)) == NC - 1) {
            const int par = (c >> 4) & 1;
            const float* qp = q_s + par * 128;
            const float* wp = wv_s + par * 128;
            #pragma unroll
            for (int mi = 0; mi < 2; ++mi) {
                #pragma unroll
                for (int ni = 0; ni < 8; ++ni) {
                    const int col0 = wn * 64 + ni * 8 + (lane & 3) * 2;
                    const float q0 = qp[col0],  q1 = qp[col0 + 1];
                    const float w0 = wp[col0],  w1 = wp[col0 + 1];
                    float* cp = acc[mi][ni];
                    const float p0 = tanhf(cp[0] + q0) * w0 + tanhf(cp[1] + q1) * w1;
                    const float p1 = tanhf(cp[2] + q0) * w0 + tanhf(cp[3] + q1) * w1;
                    if (mi == 0) { sc00 += p0; sc01 += p1; }
                    else         { sc10 += p0; sc11 += p1; }
                    cp[0] = cp[1] = cp[2] = cp[3] = 0.f;
                }
            }
        }
    }

    // ---------- final reduction ----------
    sc00 += __shfl_xor_sync(~0u, sc00, 1); sc00 += __shfl_xor_sync(~0u, sc00, 2);
    sc01 += __shfl_xor_sync(~0u, sc01, 1); sc01 += __shfl_xor_sync(~0u, sc01, 2);
    sc10 += __shfl_xor_sync(~0u, sc10, 1); sc10 += __shfl_xor_sync(~0u, sc10, 2);
    sc11 += __shfl_xor_sync(~0u, sc11, 1); sc11 += __shfl_xor_sync(~0u, sc11, 2);
    if ((lane & 3) == 0) {
        const int g = lane >> 2;
        red[wn * 128 + wm * 32 + g]      = sc00;
        red[wn * 128 + wm * 32 + 8 + g]  = sc01;
        red[wn * 128 + wm * 32 + 16 + g] = sc10;
        red[wn * 128 + wm * 32 + 24 + g] = sc11;
    }
    __syncthreads();
    if (tid < MT) out[m0 + tid] = red[tid] + red[128 + tid];
}

// ================= launch =================
extern "C" void kernel_launch(void* const* d_in, const int* in_sizes, int n_in,
                              void* d_out, int out_size) {
    const float* queries = (const float*)d_in[0];  // [16,1,1024]
    const float* keys    = (const float*)d_in[1];  // [16,8192,1024]
    const float* Wq      = (const float*)d_in[2];  // [1024,1024]
    const float* Wk      = (const float*)d_in[3];  // [1024,1024]
    const float* wv      = (const float*)d_in[4];  // [1024,1]
    float* out = (float*)d_out;                    // [16,8192]

    cudaFuncSetAttribute(additive_attn_main,
                         cudaFuncAttributeMaxDynamicSharedMemorySize, SMEM_TOTAL);

    convert_keys_kernel<<<2048, 256>>>(keys);
    wsplit_kernel<<<dim3(HH / 32, DD / 32), dim3(32, 8)>>>(Wk);
    qproj_kernel<<<dim3(HH / 256, BB), 256>>>(queries, Wq);
    additive_attn_main<<<MTOT / MT, THREADS, SMEM_TOTAL>>>(wv, out);
}